// round 2
// baseline (speedup 1.0000x reference)
#include <cuda_runtime.h>
#include <cstdint>
#include <cstdio>

// Problem constants (CentroidLayer: B=131072, P=64, D=256)
#define Dk 256
#define Pk 64
#define TQ 64          // queries per block
#define THREADS 512    // 16 warps, 4 queries per warp
#define PITCH_PK 258   // [p][k] pitch (even for 8B-aligned float2, bank shift 2)
#define PITCH_DP 66    // [d][p] pitch (even, bank shift 2)

typedef unsigned long long u64;

__device__ __forceinline__ void fma2(u64 &acc, u64 a, u64 b) {
    asm("fma.rn.f32x2 %0, %1, %2, %0;" : "+l"(acc) : "l"(a), "l"(b));
}
__device__ __forceinline__ float2 u2f(u64 v) {
    float2 r;
    asm("mov.b64 {%0,%1}, %2;" : "=f"(r.x), "=f"(r.y) : "l"(v));
    return r;
}
__device__ __forceinline__ float wsum(float v) {
#pragma unroll
    for (int o = 16; o; o >>= 1) v += __shfl_xor_sync(0xffffffffu, v, o);
    return v;
}

__global__ __launch_bounds__(THREADS)
void centroid_kernel(const float* __restrict__ qemb,
                     const float* __restrict__ cemb,
                     const unsigned char* __restrict__ mask,
                     float* __restrict__ ctx_out,
                     float* __restrict__ w_out,
                     float* __restrict__ h_out,
                     int B, int has_w, int has_h)
{
    extern __shared__ float sm[];
    float* c_pk    = sm;                         // [Pk][PITCH_PK]  raw centroids, k-contig
    float* c_dp    = c_pk + Pk * PITCH_PK;       // [Dk][PITCH_DP]  raw centroids, p-contig
    float* qn_s    = c_dp + Dk * PITCH_DP;       // [TQ][Dk]        normalized queries
    float* wbuf    = qn_s + TQ * Dk;             // [TQ][Pk]        softmax weights
    float* scale_s = wbuf + TQ * Pk;             // [Pk]            1/max(||c_p||,eps)
    float* act_s   = scale_s + Pk;               // [Pk]            active flags (1/0)

    const int tid  = threadIdx.x;
    const int lane = tid & 31;
    const int wid  = tid >> 5;

    // ---- stage centroids into both layouts ----
    for (int idx = tid; idx < Pk * Dk; idx += THREADS) {
        int p = idx >> 8, d = idx & 255;
        float v = cemb[idx];
        c_pk[p * PITCH_PK + d] = v;
        c_dp[d * PITCH_DP + p] = v;
    }
    if (tid < Pk) {
        // active_mask dtype defense: bool(1B) expected; detect int32 layout
        bool i32 = (mask[0] != 0 && mask[1] == 0 && mask[2] == 0 && mask[3] == 0);
        bool a = i32 ? (((const int*)mask)[tid] != 0) : (mask[tid] != 0);
        act_s[tid] = a ? 1.0f : 0.0f;
    }
    __syncthreads();

    // ---- centroid inverse norms: warp wid handles p = wid*4 .. +3 ----
#pragma unroll
    for (int pi = 0; pi < 4; pi++) {
        int p = wid * 4 + pi;
        float ss = 0.f;
#pragma unroll
        for (int j = 0; j < 8; j++) {
            float v = c_pk[p * PITCH_PK + lane + 32 * j];
            ss += v * v;
        }
        ss = wsum(ss);
        if (lane == 0) scale_s[p] = 1.0f / fmaxf(sqrtf(ss), 1e-12f);
    }
    __syncthreads();

    const int qbase = blockIdx.x * TQ + wid * 4;  // this warp's first query

    // ---- Phase A: load + L2-normalize 4 queries into qn_s ----
#pragma unroll
    for (int qi = 0; qi < 4; qi++) {
        int b = qbase + qi;
        if (b >= B) break;
        const float* qp = qemb + (size_t)b * Dk;
        float v[8];
        float ss = 0.f;
#pragma unroll
        for (int j = 0; j < 8; j++) {
            v[j] = qp[lane + 32 * j];
            ss += v[j] * v[j];
        }
        ss = wsum(ss);
        float inv = 1.0f / fmaxf(sqrtf(ss), 1e-12f);
        float* qs = qn_s + (wid * 4 + qi) * Dk;
#pragma unroll
        for (int j = 0; j < 8; j++) qs[lane + 32 * j] = v[j] * inv;
    }
    __syncwarp();

    // ---- Phase B: sims. lane owns p=lane and p=lane+32; f32x2 over k-pairs ----
    u64 acc[4][2] = {};
    const u64* ctA = (const u64*)(c_pk + lane * PITCH_PK);
    const u64* ctB = (const u64*)(c_pk + (lane + 32) * PITCH_PK);
    const u64* qv[4];
#pragma unroll
    for (int qi = 0; qi < 4; qi++) qv[qi] = (const u64*)(qn_s + (wid * 4 + qi) * Dk);

#pragma unroll 4
    for (int kk = 0; kk < Dk / 2; kk++) {
        u64 va = ctA[kk], vb = ctB[kk];
#pragma unroll
        for (int qi = 0; qi < 4; qi++) {
            u64 q2 = qv[qi][kk];
            fma2(acc[qi][0], q2, va);
            fma2(acc[qi][1], q2, vb);
        }
    }

    // ---- Phase C: mask + softmax + argmax per query ----
    const float sA = scale_s[lane], sB = scale_s[lane + 32];
    const float aA = act_s[lane],   aB = act_s[lane + 32];
    float w0[4], w1[4];
    int amax[4];
#pragma unroll
    for (int qi = 0; qi < 4; qi++) {
        float2 t0 = u2f(acc[qi][0]);
        float2 t1 = u2f(acc[qi][1]);
        float s0 = (t0.x + t0.y) * sA;
        float s1 = (t1.x + t1.y) * sB;
        s0 = (aA != 0.f) ? s0 : -1e9f;
        s1 = (aB != 0.f) ? s1 : -1e9f;
        float m; int mi;
        if (s1 > s0) { m = s1; mi = lane + 32; } else { m = s0; mi = lane; }
#pragma unroll
        for (int o = 16; o; o >>= 1) {
            float om = __shfl_xor_sync(0xffffffffu, m, o);
            int   oi = __shfl_xor_sync(0xffffffffu, mi, o);
            if (om > m || (om == m && oi < mi)) { m = om; mi = oi; }
        }
        float e0 = __expf(s0 - m), e1 = __expf(s1 - m);
        float sum = wsum(e0 + e1);
        float inv = 1.0f / sum;
        w0[qi] = e0 * inv;
        w1[qi] = e1 * inv;
        amax[qi] = mi;
    }
#pragma unroll
    for (int qi = 0; qi < 4; qi++) {
        int b = qbase + qi;
        if (b >= B) break;
        float* wq = wbuf + (wid * 4 + qi) * Pk;
        wq[lane] = w0[qi];
        wq[lane + 32] = w1[qi];
        if (has_w) {
            w_out[(size_t)b * Pk + lane]      = w0[qi];
            w_out[(size_t)b * Pk + lane + 32] = w1[qi];
        }
        if (has_h && lane == 0) h_out[b] = (float)amax[qi];
    }
    __syncwarp();

    // ---- Phase D: context = W @ C, f32x2 over p-pairs, lane owns d=lane+32*j ----
#pragma unroll
    for (int pass = 0; pass < 2; pass++) {
        u64 cacc[4][4] = {};
#pragma unroll 8
        for (int pp = 0; pp < Pk / 2; pp++) {
            u64 cv[4];
#pragma unroll
            for (int jj = 0; jj < 4; jj++) {
                int d = lane + 32 * (pass * 4 + jj);
                cv[jj] = *(const u64*)(c_dp + d * PITCH_DP + 2 * pp);
            }
#pragma unroll
            for (int qi = 0; qi < 4; qi++) {
                u64 w2 = *(const u64*)(wbuf + (wid * 4 + qi) * Pk + 2 * pp);
#pragma unroll
                for (int jj = 0; jj < 4; jj++) fma2(cacc[qi][jj], w2, cv[jj]);
            }
        }
#pragma unroll
        for (int qi = 0; qi < 4; qi++) {
            int b = qbase + qi;
            if (b >= B) break;
#pragma unroll
            for (int jj = 0; jj < 4; jj++) {
                float2 t = u2f(cacc[qi][jj]);
                ctx_out[(size_t)b * Dk + lane + 32 * (pass * 4 + jj)] = t.x + t.y;
            }
        }
    }
}

extern "C" void kernel_launch(void* const* d_in, const int* in_sizes, int n_in,
                              void* d_out, int out_size)
{
    const float* q = (const float*)d_in[0];
    const float* c = (const float*)d_in[1];
    const unsigned char* m = (const unsigned char*)d_in[2];

    const int PD = in_sizes[1];            // P*D
    const int Pn = in_sizes[2];            // P
    const int Dn = PD / Pn;                // D
    const int Bn = in_sizes[0] / Dn;       // B

    float* out = (float*)d_out;
    const long long woff = (long long)Bn * Dn;
    const long long hoff = woff + (long long)Bn * Pn;
    const int has_w = ((long long)out_size >= woff + (long long)Bn * Pn) ? 1 : 0;
    const int has_h = ((long long)out_size >= hoff + (long long)Bn) ? 1 : 0;

    const size_t smem = (size_t)(Pk * PITCH_PK + Dk * PITCH_DP + TQ * Dk +
                                 TQ * Pk + Pk + Pk) * sizeof(float);
    cudaFuncSetAttribute(centroid_kernel,
                         cudaFuncAttributeMaxDynamicSharedMemorySize, (int)smem);

    const int grid = (Bn + TQ - 1) / TQ;
    centroid_kernel<<<grid, THREADS, smem>>>(q, c, m, out, out + woff, out + hoff,
                                             Bn, has_w, has_h);
}